// round 17
// baseline (speedup 1.0000x reference)
#include <cuda_runtime.h>
#include <math.h>

// Problem constants (fixed by reference setup_inputs)
#define B  4
#define T  4096
#define C  64
#define HS 64
#define BT (B * T)

// Streams with priorities + fork/join events, created once at init.
static cudaStream_t g_sZero;   // low priority  : bulk zero-fill
static cudaStream_t g_sComp;   // high priority : fused qkv+band
static cudaEvent_t  g_evFork, g_evZ, g_evC;
namespace {
struct InitStreams {
    InitStreams() {
        int leastPrio = 0, greatestPrio = 0;
        cudaDeviceGetStreamPriorityRange(&leastPrio, &greatestPrio);
        cudaStreamCreateWithPriority(&g_sZero, cudaStreamNonBlocking, leastPrio);
        cudaStreamCreateWithPriority(&g_sComp, cudaStreamNonBlocking, greatestPrio);
        cudaEventCreateWithFlags(&g_evFork, cudaEventDisableTiming);
        cudaEventCreateWithFlags(&g_evZ, cudaEventDisableTiming);
        cudaEventCreateWithFlags(&g_evC, cudaEventDisableTiming);
    }
};
InitStreams g_initStreams;
}

typedef unsigned long long u64;
__device__ __forceinline__ u64 pack2(float a) {
    u64 r;
    asm("mov.b64 %0, {%1, %1};" : "=l"(r) : "f"(a));
    return r;
}
__device__ __forceinline__ void ffma2(u64& acc, u64 a, u64 b) {
    asm("fma.rn.f32x2 %0, %1, %2, %0;" : "+l"(acc) : "l"(a), "l"(b));
}

// ---------------------------------------------------------------------------
// Kernel Z: zero-fill the attn matrix, skipping the <=2 band float4 slots per
// row (the fused kernel writes those at disjoint addresses). One warp per row.
// 0 smem, 16 regs -> backfills free warp slots alongside the fused kernel.
// ---------------------------------------------------------------------------
__global__ __launch_bounds__(256, 8)
void zero_kernel(float* __restrict__ attn_out)   // [B, T, T]
{
    const int warp_in_blk = threadIdx.x >> 5;
    const int lane = threadIdx.x & 31;
    const int w = blockIdx.x * 8 + warp_in_blk;   // row id in [0, BT)
    const int b = w >> 12;
    const int t = w & (T - 1);

    const int lo = max(t - 2, 0);
    const int hi = min(t + 2, T - 1);
    const int fa = lo >> 2;
    const int fb = hi >> 2;

    float4* row4 = reinterpret_cast<float4*>(
        attn_out + (size_t)b * T * T + (size_t)t * T);
    const float4 z = make_float4(0.f, 0.f, 0.f, 0.f);

    #pragma unroll 4
    for (int i4 = lane; i4 < T / 4; i4 += 32) {
        if (i4 != fa && i4 != fb) __stcs(&row4[i4], z);
    }
}

// ---------------------------------------------------------------------------
// Fused QKV + band kernel. Grid 256 (wave-1 resident at 2 blocks/SM), block
// 256 threads, ~90 KB dynamic smem. Each block owns 64 rows:
//   halo row indexing (i in xs / qkv_s):  0..63 = own rows t0..t0+63,
//   64,65 = t0-2, t0-1 (pre-halo), 66,67 = t0+64, t0+65 (post-halo).
//   Own rows sit at the array base so GEMM float4 loads stay 16B-aligned.
// Steps: load x halo -> per matrix {load W, 4x4 ffma2 GEMM on own rows,
// halo rows for k/v} -> in-smem band softmax + op rows + band float4 slots.
// No global scratch, no separate band launch.
// ---------------------------------------------------------------------------
#define XST 72   // xs row stride  (floats, mult of 4)
#define WST 68   // ws row stride  (floats, mult of 4)
#define OST 66   // qkv_s row stride (floats, even)
#define FUSED_SMEM_BYTES ((64 * XST + 64 * WST + 3 * 68 * OST) * 4)  // 89696 B

__global__ __launch_bounds__(256)
void fused_kernel(const float* __restrict__ x,
                  const float* __restrict__ Wq,
                  const float* __restrict__ Wk,
                  const float* __restrict__ Wv,
                  float* __restrict__ op_out,    // [B*T, 64]
                  float* __restrict__ attn_out)  // [B, T, T]
{
    extern __shared__ float sm[];
    float* xs = sm;                        // xs[c*XST + i]
    float* ws = xs + 64 * XST;             // ws[c*WST + h]
    float* qkv_s = ws + 64 * WST;          // qkv_s[m*68*OST + i*OST + h]

    const int tid = threadIdx.x;
    const int r0 = blockIdx.x * 64;        // global row base
    const int bb = r0 >> 12;               // batch
    const int t0 = r0 & (T - 1);           // row base within batch

    // ---- load x halo (68 rows), transposed into xs[c][i] ----
    #pragma unroll
    for (int idx = tid; idx < 68 * 64; idx += 256) {
        const int i = idx >> 6, c = idx & 63;
        // map halo slot i -> row offset j relative to t0
        const int j = (i < 64) ? i : ((i < 66) ? (i - 66) : (i - 2));
        const int tb = min(max(t0 + j, 0), T - 1);
        xs[c * XST + i] = x[((size_t)(bb * T + tb)) * C + c];
    }

    const float* Wm[3] = {Wq, Wk, Wv};

    const int tm = (tid >> 4) * 4;   // own-row group: 0..60 (16B-aligned)
    const int tn = (tid & 15) * 4;   // col group: 0..60

    #pragma unroll 1
    for (int m = 0; m < 3; ++m) {
        // load W transposed: ws[c][h]
        #pragma unroll
        for (int idx = tid; idx < 64 * 64; idx += 256) {
            const int h = idx >> 6, c = idx & 63;
            ws[c * WST + h] = Wm[m][idx];
        }
        __syncthreads();

        float* outm = &qkv_s[m * 68 * OST];

        // ---- own 64 rows: 4x4 thread tile, packed ffma2 ----
        u64 acc[4][2];
        #pragma unroll
        for (int i = 0; i < 4; i++) { acc[i][0] = 0ULL; acc[i][1] = 0ULL; }

        #pragma unroll 4
        for (int c = 0; c < 64; ++c) {
            const float4 a4 =
                *reinterpret_cast<const float4*>(&xs[c * XST + tm]);
            const ulonglong2 bv =
                *reinterpret_cast<const ulonglong2*>(&ws[c * WST + tn]);
            const u64 b0 = bv.x, b1 = bv.y;
            u64 p;
            p = pack2(a4.x); ffma2(acc[0][0], p, b0); ffma2(acc[0][1], p, b1);
            p = pack2(a4.y); ffma2(acc[1][0], p, b0); ffma2(acc[1][1], p, b1);
            p = pack2(a4.z); ffma2(acc[2][0], p, b0); ffma2(acc[2][1], p, b1);
            p = pack2(a4.w); ffma2(acc[3][0], p, b0); ffma2(acc[3][1], p, b1);
        }
        #pragma unroll
        for (int i = 0; i < 4; i++) {
            u64* o = reinterpret_cast<u64*>(&outm[(tm + i) * OST + tn]);
            o[0] = acc[i][0];
            o[1] = acc[i][1];
        }

        // ---- halo rows (idx 64..67), k/v only ----
        if (m > 0) {
            const int hr = tid >> 6;       // 0..3
            const int h = tid & 63;
            float a = 0.0f;
            #pragma unroll 8
            for (int c = 0; c < 64; ++c)
                a += xs[c * XST + 64 + hr] * ws[c * WST + h];
            outm[(64 + hr) * OST + h] = a;
        }
        __syncthreads();
    }

    // ---- band: warp wid handles own rows wid*8 .. wid*8+7 ----
    const int wid = tid >> 5;
    const int lane = tid & 31;
    const float* q_s = qkv_s;                   // m=0
    const float* k_s = qkv_s + 68 * OST;        // m=1
    const float* v_s = qkv_s + 2 * 68 * OST;    // m=2

    #pragma unroll
    for (int rr = 0; rr < 8; ++rr) {
        const int lr = wid * 8 + rr;       // 0..63
        const int t = t0 + lr;
        const int w = r0 + lr;

        const float2 q2 = *reinterpret_cast<const float2*>(
            &q_s[lr * OST + 2 * lane]);

        float score[5];
        #pragma unroll
        for (int d = 0; d < 5; ++d) {
            const int s = t - 2 + d;
            const bool valid = (unsigned)s < (unsigned)T;
            float p = 0.0f;
            if (valid) {
                const int j = lr - 2 + d;
                const int hi_ = (j < 0) ? (j + 66) : ((j >= 64) ? (j + 2) : j);
                const float2 k2 = *reinterpret_cast<const float2*>(
                    &k_s[hi_ * OST + 2 * lane]);
                p = q2.x * k2.x + q2.y * k2.y;
            }
            #pragma unroll
            for (int off = 16; off > 0; off >>= 1)
                p += __shfl_xor_sync(0xFFFFFFFFu, p, off);
            // scale = C^-0.5 = 1/8 ; triu quirk: +1.0 when s > t (d > 2)
            score[d] = valid ? (p * 0.125f + (d > 2 ? 1.0f : 0.0f)) : -1e30f;
        }

        float mmax = score[0];
        #pragma unroll
        for (int d = 1; d < 5; ++d) mmax = fmaxf(mmax, score[d]);
        float p5[5], sum = 0.0f;
        #pragma unroll
        for (int d = 0; d < 5; ++d) {
            p5[d] = expf(score[d] - mmax);
            sum += p5[d];
        }
        const float inv = 1.0f / sum;
        #pragma unroll
        for (int d = 0; d < 5; ++d) p5[d] *= inv;

        // op row: each lane owns 2 channels
        float2 acc2 = make_float2(0.0f, 0.0f);
        #pragma unroll
        for (int d = 0; d < 5; ++d) {
            const int s = t - 2 + d;
            if ((unsigned)s < (unsigned)T) {
                const int j = lr - 2 + d;
                const int hi_ = (j < 0) ? (j + 66) : ((j >= 64) ? (j + 2) : j);
                const float2 v2 = *reinterpret_cast<const float2*>(
                    &v_s[hi_ * OST + 2 * lane]);
                acc2.x += p5[d] * v2.x;
                acc2.y += p5[d] * v2.y;
            }
        }
        *reinterpret_cast<float2*>(&op_out[(size_t)w * HS + 2 * lane]) = acc2;

        // band float4 slots (zero kernel skips these)
        const int lo = max(t - 2, 0);
        const int hi = min(t + 2, T - 1);
        const int fa = lo >> 2;
        const int fb = hi >> 2;
        #define BV(s_) (((s_) >= lo && (s_) <= hi)                            \
                          ? ((s_) == t - 2 ? p5[0]                            \
                           : (s_) == t - 1 ? p5[1]                            \
                           : (s_) == t     ? p5[2]                            \
                           : (s_) == t + 1 ? p5[3] : p5[4])                   \
                          : 0.0f)
        const float4 va = make_float4(BV(4 * fa + 0), BV(4 * fa + 1),
                                      BV(4 * fa + 2), BV(4 * fa + 3));
        const float4 vb = make_float4(BV(4 * fb + 0), BV(4 * fb + 1),
                                      BV(4 * fb + 2), BV(4 * fb + 3));
        #undef BV

        float4* row4 = reinterpret_cast<float4*>(
            attn_out + (size_t)bb * T * T + (size_t)t * T);
        if (lane == 0) __stcs(&row4[fa], va);
        if (lane == 1 && fb != fa) __stcs(&row4[fb], vb);
    }
}

// ---------------------------------------------------------------------------
extern "C" void kernel_launch(void* const* d_in, const int* in_sizes, int n_in,
                              void* d_out, int out_size)
{
    const float* x  = (const float*)d_in[0];
    const float* Wq = (const float*)d_in[1];
    const float* Wk = (const float*)d_in[2];
    const float* Wv = (const float*)d_in[3];

    float* out = (float*)d_out;
    float* op_out   = out;                     // [B*T*HS]
    float* attn_out = out + (size_t)BT * HS;   // [B*T*T]

    cudaFuncSetAttribute(fused_kernel,
                         cudaFuncAttributeMaxDynamicSharedMemorySize,
                         FUSED_SMEM_BYTES);

    // Fork from the capture stream into both priority streams.
    cudaEventRecord(g_evFork, 0);
    cudaStreamWaitEvent(g_sComp, g_evFork, 0);
    cudaStreamWaitEvent(g_sZero, g_evFork, 0);

    // fused (256 blocks, 2/SM capacity 296 -> wave-1 resident) enqueued
    // first; zero's 0-smem blocks backfill the remaining warp slots from
    // t~0 and run pure stores for the whole duration. No third launch.
    fused_kernel<<<BT / 64, 256, FUSED_SMEM_BYTES, g_sComp>>>(
        x, Wq, Wk, Wv, op_out, attn_out);

    zero_kernel<<<BT / 8, 256, 0, g_sZero>>>(attn_out);

    // Join both streams back into the capture stream.
    cudaEventRecord(g_evC, g_sComp);
    cudaStreamWaitEvent(0, g_evC, 0);
    cudaEventRecord(g_evZ, g_sZero);
    cudaStreamWaitEvent(0, g_evZ, 0);
}